// round 16
// baseline (speedup 1.0000x reference)
#include <cuda_runtime.h>
#include <cuda_bf16.h>
#include <math.h>

#define N_SEQ 896
#define DH    3072
#define NC    64
#define NJ    127
#define DC    1024
#define INNER 512
#define NH    8
#define HD    64
#define MPAD  8192

// ---------------- scratch ----------------
__device__ float g_w[INNER];
__device__ float g_ep[N_SEQ];
__device__ float g_bias;
__device__ float g_wvpt[NH * DC];
__device__ float g_vpnull[NH];
__device__ float g_vpt[NC * NH * NJ];
__device__ __nv_bfloat16 g_nullk_hi[INNER];
__device__ __nv_bfloat16 g_nullk_lo[INNER];
__device__ float g_kp[(size_t)4 * MPAD * INNER];
__device__ float g_qp[(size_t)12 * N_SEQ * INNER];
__device__ __nv_bfloat16 g_a_hi[(size_t)MPAD * DC];
__device__ __nv_bfloat16 g_a_lo[(size_t)MPAD * DC];
__device__ __nv_bfloat16 g_aq_hi[(size_t)N_SEQ * DH];
__device__ __nv_bfloat16 g_aq_lo[(size_t)N_SEQ * DH];
__device__ __nv_bfloat16 g_wk_hi[(size_t)INNER * DC];
__device__ __nv_bfloat16 g_wk_lo[(size_t)INNER * DC];
__device__ __nv_bfloat16 g_wq_hi[(size_t)INNER * DH];
__device__ __nv_bfloat16 g_wq_lo[(size_t)INNER * DH];
__device__ __nv_bfloat16 g_q_hi[(size_t)N_SEQ * INNER];
__device__ __nv_bfloat16 g_q_lo[(size_t)N_SEQ * INNER];
__device__ __nv_bfloat16 g_k_hi[(size_t)MPAD * INNER];
__device__ __nv_bfloat16 g_k_lo[(size_t)MPAD * INNER];

__device__ __forceinline__ float warpSum(float v) {
#pragma unroll
    for (int o = 16; o > 0; o >>= 1) v += __shfl_xor_sync(0xffffffffu, v, o);
    return v;
}
__device__ __forceinline__ unsigned b2u(__nv_bfloat162 h) {
    return *reinterpret_cast<unsigned*>(&h);
}
__device__ __forceinline__ unsigned smem_u32(const void* p) {
    unsigned a;
    asm("{ .reg .u64 t; cvta.to.shared.u64 t, %1; cvt.u32.u64 %0, t; }" : "=r"(a) : "l"(p));
    return a;
}
__device__ __forceinline__ unsigned sw128(unsigned o) { return o ^ ((o >> 3) & 0x70); }
__device__ __forceinline__ unsigned pk(unsigned row, unsigned kbyte) {
    unsigned base = ((row >> 1) << 7) + ((row & 1) << 6) + kbyte;
    return base ^ ((base >> 3) & 0x70);
}
__device__ __forceinline__ float fexp2(float x) {
    float r; asm("ex2.approx.f32 %0, %1;" : "=f"(r) : "f"(x)); return r;
}
__device__ __forceinline__ void ldm_x4(unsigned* r, unsigned addr) {
    asm volatile("ldmatrix.sync.aligned.m8n8.x4.shared.b16 {%0,%1,%2,%3}, [%4];"
        : "=r"(r[0]), "=r"(r[1]), "=r"(r[2]), "=r"(r[3]) : "r"(addr));
}
__device__ __forceinline__ void mma_bf16(float* d, const unsigned* a, const unsigned* b) {
    asm volatile("mma.sync.aligned.m16n8k16.row.col.f32.bf16.bf16.f32 "
        "{%0,%1,%2,%3}, {%4,%5,%6,%7}, {%8,%9}, {%0,%1,%2,%3};"
        : "+f"(d[0]), "+f"(d[1]), "+f"(d[2]), "+f"(d[3])
        : "r"(a[0]), "r"(a[1]), "r"(a[2]), "r"(a[3]), "r"(b[0]), "r"(b[1]));
}
__device__ __forceinline__ void cpa16(unsigned dst, const void* src) {
    asm volatile("cp.async.cg.shared.global [%0], [%1], 16;" :: "r"(dst), "l"(src));
}
#define CPA_COMMIT() asm volatile("cp.async.commit_group;" ::: "memory")
#define CPA_WAIT1()  asm volatile("cp.async.wait_group 1;" ::: "memory")
#define CPA_WAIT0()  asm volatile("cp.async.wait_group 0;" ::: "memory")

__device__ __forceinline__ void split2(float x, float y, unsigned& hi, unsigned& lo) {
    __nv_bfloat162 h = __float22bfloat162_rn(make_float2(x, y));
    __nv_bfloat162 l = __float22bfloat162_rn(make_float2(
        x - __bfloat162float(h.x), y - __bfloat162float(h.y)));
    hi = b2u(h); lo = b2u(l);
}

// ---------------- stream-2 chain: dots -> prep2 -> ln_c ----------------
__global__ void k_dots(const float* __restrict__ Wo, const float* __restrict__ Wp,
                       const float* __restrict__ bo, const float* __restrict__ bp) {
    __shared__ float red[8];
    int id = blockIdx.x, t = threadIdx.x;
    const float* a = (id < 512) ? (Wo + (size_t)id * DH) : bo;
    float s = 0.f;
    for (int i = t; i < DH; i += 256) s = fmaf(a[i], Wp[i], s);
    s = warpSum(s);
    if ((t & 31) == 0) red[t >> 5] = s;
    __syncthreads();
    if (t == 0) {
        float S = 0.f;
#pragma unroll
        for (int i = 0; i < 8; i++) S += red[i];
        if (id < 512) g_w[id] = S;
        else          g_bias = S + bp[0];
    }
}

__global__ void k_prep2(const float* __restrict__ Wkv, const float* __restrict__ null_v,
                        const float* __restrict__ null_k) {
    int bid = blockIdx.x, t = threadIdx.x;
    if (bid < 32) {
        int gid = bid * 256 + t;
        int h = gid >> 10, i = gid & 1023;
        const float* wrow = g_w + h * HD;
        const float* src  = Wkv + (size_t)i * (2 * INNER) + INNER + h * HD;
        float s = 0.f;
#pragma unroll
        for (int d = 0; d < HD; d++) s = fmaf(src[d], wrow[d], s);
        g_wvpt[h * DC + i] = s;
    } else {
        if (t < NH) {
            float s = 0.f;
#pragma unroll
            for (int d = 0; d < HD; d++) s = fmaf(null_v[t * HD + d], g_w[t * HD + d], s);
            g_vpnull[t] = s;
        }
        for (int i = t; i < INNER; i += 256) {
            float v = null_k[i];
            __nv_bfloat16 hb = __float2bfloat16_rn(v);
            g_nullk_hi[i] = hb;
            g_nullk_lo[i] = __float2bfloat16_rn(v - __bfloat162float(hb));
        }
    }
}

__global__ __launch_bounds__(256) void k_ln_c(const float* __restrict__ x,
                                              const float* __restrict__ gamma,
                                              const float* __restrict__ beta) {
    __shared__ float wvs[NH * DC];
    int t = threadIdx.x, warp = t >> 5, lane = t & 31;
    for (int i = t; i < NH * DC; i += 256) wvs[i] = g_wvpt[i];
    __syncthreads();

    int b = blockIdx.x * 8 + warp;
    if (b >= NC * NJ) {
        if (b < MPAD) {
            uint2 z = make_uint2(0u, 0u);
#pragma unroll
            for (int c = 0; c < 8; c++) {
                size_t off = (size_t)b * DC + c * 128 + lane * 4;
                *(uint2*)(g_a_hi + off) = z;
                *(uint2*)(g_a_lo + off) = z;
            }
        }
        return;
    }
    const float* xr = x + (size_t)b * DC;
    float4 r[8];
    float s = 0.f, ss = 0.f;
#pragma unroll
    for (int c = 0; c < 8; c++) {
        r[c] = *(const float4*)(xr + c * 128 + lane * 4);
        s  += r[c].x + r[c].y + r[c].z + r[c].w;
        ss += r[c].x*r[c].x + r[c].y*r[c].y + r[c].z*r[c].z + r[c].w*r[c].w;
    }
    s = warpSum(s); ss = warpSum(ss);
    float mu = s / DC;
    float rstd = rsqrtf(ss / DC - mu * mu + 1e-5f);
#pragma unroll
    for (int c = 0; c < 8; c++) {
        int idx = c * 128 + lane * 4;
        float4 g = *(const float4*)(gamma + idx);
        float4 bb = *(const float4*)(beta + idx);
        r[c].x = (r[c].x - mu) * rstd * g.x + bb.x;
        r[c].y = (r[c].y - mu) * rstd * g.y + bb.y;
        r[c].z = (r[c].z - mu) * rstd * g.z + bb.z;
        r[c].w = (r[c].w - mu) * rstd * g.w + bb.w;
        unsigned h01, l01, h23, l23;
        split2(r[c].x, r[c].y, h01, l01); split2(r[c].z, r[c].w, h23, l23);
        size_t off = (size_t)b * DC + idx;
        *(uint2*)(g_a_hi + off) = make_uint2(h01, h23);
        *(uint2*)(g_a_lo + off) = make_uint2(l01, l23);
    }
    int cc = b / NJ, j = b % NJ;
#pragma unroll
    for (int h = 0; h < NH; h++) {
        float acc = 0.f;
#pragma unroll
        for (int c = 0; c < 8; c++) {
            int idx = h * DC + c * 128 + lane * 4;
            acc = fmaf(r[c].x, wvs[idx],   acc);
            acc = fmaf(r[c].y, wvs[idx+1], acc);
            acc = fmaf(r[c].z, wvs[idx+2], acc);
            acc = fmaf(r[c].w, wvs[idx+3], acc);
        }
        acc = warpSum(acc);
        if (lane == 0) g_vpt[((size_t)cc * NH + h) * NJ + j] = acc;
    }
}

// ---------------- main-stream prologue: LN(emb)+ep + weight conversions -------
__global__ void k_megaB(const float* __restrict__ emb, const float* __restrict__ gamma,
                        const float* __restrict__ beta, const float* __restrict__ Wp,
                        const float* __restrict__ Wkv, const float* __restrict__ Wq) {
    __shared__ float row[DH];
    __shared__ float red[26];
    int bid = blockIdx.x, t = threadIdx.x;

    if (bid < N_SEQ) {
        const float* xr = emb + (size_t)bid * DH;
        float s = 0.f, ss = 0.f, se = 0.f;
#pragma unroll
        for (int u = 0; u < 3; u++) {
            int idx = (t + u * 256) * 4;
            float4 v = *(const float4*)(xr + idx);
            float4 w = *(const float4*)(Wp + idx);
            row[idx] = v.x; row[idx+1] = v.y; row[idx+2] = v.z; row[idx+3] = v.w;
            s  += v.x + v.y + v.z + v.w;
            ss += v.x*v.x + v.y*v.y + v.z*v.z + v.w*v.w;
            se += v.x*w.x + v.y*w.y + v.z*w.z + v.w*w.w;
        }
        s = warpSum(s); ss = warpSum(ss); se = warpSum(se);
        if ((t & 31) == 0) { int w8 = t >> 5; red[w8] = s; red[8+w8] = ss; red[16+w8] = se; }
        __syncthreads();
        if (t == 0) {
            float S = 0.f, SS = 0.f, SE = 0.f;
#pragma unroll
            for (int i = 0; i < 8; i++) { S += red[i]; SS += red[8+i]; SE += red[16+i]; }
            float mu = S / DH;
            float var = SS / DH - mu * mu;
            red[24] = mu; red[25] = rsqrtf(var + 1e-5f);
            g_ep[bid] = SE;
        }
        __syncthreads();
        float mu = red[24], rstd = red[25];
#pragma unroll
        for (int u = 0; u < 3; u++) {
            int idx = (t + u * 256) * 4;
            float o0 = (row[idx]   - mu) * rstd * gamma[idx]   + beta[idx];
            float o1 = (row[idx+1] - mu) * rstd * gamma[idx+1] + beta[idx+1];
            float o2 = (row[idx+2] - mu) * rstd * gamma[idx+2] + beta[idx+2];
            float o3 = (row[idx+3] - mu) * rstd * gamma[idx+3] + beta[idx+3];
            unsigned h01, l01, h23, l23;
            split2(o0, o1, h01, l01); split2(o2, o3, h23, l23);
            size_t off = (size_t)bid * DH + idx;
            *(uint2*)(g_aq_hi + off) = make_uint2(h01, h23);
            *(uint2*)(g_aq_lo + off) = make_uint2(l01, l23);
        }
        return;
    }
    {
        float (*tile)[33] = (float(*)[33])row;
        const float* src; __nv_bfloat16 *dh, *dl;
        int K, ldsrc, k0, n0;
        int l = bid - N_SEQ;
        if (l < 512) {
            K = DC; ldsrc = 2 * INNER; src = Wkv; dh = g_wk_hi; dl = g_wk_lo;
            k0 = (l & 31) * 32; n0 = (l >> 5) * 32;
        } else {
            int l2 = l - 512;
            K = DH; ldsrc = INNER; src = Wq; dh = g_wq_hi; dl = g_wq_lo;
            k0 = (l2 % 96) * 32; n0 = (l2 / 96) * 32;
        }
        int tx = t & 31, ty = t >> 5;
#pragma unroll
        for (int r = 0; r < 4; r++)
            tile[ty + 8 * r][tx] = src[(size_t)(k0 + ty + 8 * r) * ldsrc + n0 + tx];
        __syncthreads();
#pragma unroll
        for (int r = 0; r < 4; r++) {
            int n = n0 + ty + 8 * r;
            float v = tile[tx][ty + 8 * r];
            __nv_bfloat16 h = __float2bfloat16_rn(v);
            __nv_bfloat16 l2b = __float2bfloat16_rn(v - __bfloat162float(h));
            dh[(size_t)n * K + k0 + tx] = h;
            dl[(size_t)n * K + k0 + tx] = l2b;
        }
    }
}

// ---------------- HMMA GEMM v7 (R15, unchanged) ----------
#define G2_AH 0
#define G2_AL 8192
#define G2_BH 16384
#define G2_BL 24576
#define G2_ST 32768
#define G2_SMEM (3 * G2_ST)

__global__ void __launch_bounds__(512, 2) k_gemm_mma() {
    extern __shared__ char smg[];
    unsigned sb = smem_u32(smg);
    int t = threadIdx.x, bid = blockIdx.x;

    const __nv_bfloat16 *Ahp, *Alp, *Bhp, *Blp;
    float* P;
    int Kb, m0, n0, kbase;
    if (bid < 1024) {
        int part = bid >> 8, r = bid & 255;
        m0 = (r >> 2) * 128; n0 = (r & 3) * 128;
        Ahp = g_a_hi; Alp = g_a_lo; Kb = DC; kbase = part * 256;
        Bhp = g_wk_hi; Blp = g_wk_lo;
        P = g_kp + (size_t)part * MPAD * INNER;
    } else {
        int l = bid - 1024;
        int part = l / 28, r = l % 28;
        m0 = (r >> 2) * 128; n0 = (r & 3) * 128;
        Ahp = g_aq_hi; Alp = g_aq_lo; Kb = DH; kbase = part * 256;
        Bhp = g_wq_hi; Blp = g_wq_lo;
        P = g_qp + (size_t)part * N_SEQ * INNER;
    }
    int warp = t >> 5, lane = t & 31;
    int wm = (warp & 3) * 32, wn = (warp >> 2) * 32;

    float D[2][4][4];
#pragma unroll
    for (int i = 0; i < 2; i++)
#pragma unroll
        for (int j = 0; j < 4; j++)
#pragma unroll
            for (int k = 0; k < 4; k++) D[i][j][k] = 0.f;

    int sr = t >> 2, sc = (t & 3) * 8;
    unsigned sdst = pk((unsigned)sr, (unsigned)((t & 3) * 16));
    const __nv_bfloat16* a_h = Ahp + (size_t)(m0 + sr) * Kb + kbase + sc;
    const __nv_bfloat16* a_l = Alp + (size_t)(m0 + sr) * Kb + kbase + sc;
    const __nv_bfloat16* b_h = Bhp + (size_t)(n0 + sr) * Kb + kbase + sc;
    const __nv_bfloat16* b_l = Blp + (size_t)(n0 + sr) * Kb + kbase + sc;

    const int S = 8;
    auto issue = [&](int k0, int st) {
        unsigned base = sb + st * G2_ST;
        cpa16(base + G2_AH + sdst, a_h + k0);
        cpa16(base + G2_AL + sdst, a_l + k0);
        cpa16(base + G2_BH + sdst, b_h + k0);
        cpa16(base + G2_BL + sdst, b_l + k0);
        CPA_COMMIT();
    };

    issue(0, 0);
    issue(32, 1);
    for (int s = 0; s < S; s++) {
        if (s < S - 1) CPA_WAIT1(); else CPA_WAIT0();
        __syncthreads();
        if (s + 2 < S) issue((s + 2) * 32, (s + 2) % 3);
        unsigned ab = sb + (s % 3) * G2_ST;
#pragma unroll
        for (int ks = 0; ks < 32; ks += 16) {
            unsigned ah[2][4], al[2][4];
#pragma unroll
            for (int mt = 0; mt < 2; mt++) {
                unsigned ad = pk((unsigned)(wm + mt * 16 + (lane & 15)),
                                 (unsigned)((ks + (lane >> 4) * 8) * 2));
                ldm_x4(ah[mt], ab + G2_AH + ad);
                ldm_x4(al[mt], ab + G2_AL + ad);
            }
#pragma unroll
            for (int p = 0; p < 2; p++) {
                unsigned row = (unsigned)(wn + p * 16 + ((lane >> 4) << 3) + (lane & 7));
                unsigned bd = pk(row, (unsigned)((ks + ((lane >> 3) & 1) * 8) * 2));
                unsigned bh[4], bl[4];
                ldm_x4(bh, ab + G2_BH + bd);
                mma_bf16(D[0][2*p],   ah[0], bh);
                mma_bf16(D[1][2*p],   ah[1], bh);
                mma_bf16(D[0][2*p],   al[0], bh);
                mma_bf16(D[1][2*p],   al[1], bh);
                mma_bf16(D[0][2*p+1], ah[0], bh + 2);
                mma_bf16(D[1][2*p+1], ah[1], bh + 2);
                mma_bf16(D[0][2*p+1], al[0], bh + 2);
                mma_bf16(D[1][2*p+1], al[1], bh + 2);
                ldm_x4(bl, ab + G2_BL + bd);
                mma_bf16(D[0][2*p],   ah[0], bl);
                mma_bf16(D[1][2*p],   ah[1], bl);
                mma_bf16(D[0][2*p+1], ah[0], bl + 2);
                mma_bf16(D[1][2*p+1], ah[1], bl + 2);
            }
        }
    }
#pragma unroll
    for (int mt = 0; mt < 2; mt++) {
        int r0 = m0 + wm + mt * 16 + (lane >> 2);
#pragma unroll
        for (int nt = 0; nt < 4; nt++) {
            int col = n0 + wn + nt * 8 + 2 * (lane & 3);
#pragma unroll
            for (int half = 0; half < 2; half++) {
                *(float2*)(P + (size_t)(r0 + half * 8) * INNER + col) =
                    make_float2(D[mt][nt][half * 2], D[mt][nt][half * 2 + 1]);
            }
        }
    }
}

// ---------------- split-K combine ----
__global__ __launch_bounds__(256) void k_comb() {
    int bid = blockIdx.x, t = threadIdx.x;
    if (bid < 8128) {
        size_t i = (size_t)bid * INNER + t * 2;
        const size_t NK = (size_t)MPAD * INNER;
        float x = 0.f, y = 0.f;
#pragma unroll
        for (int p = 0; p < 4; p++) {
            float2 v = *(const float2*)(g_kp + p * NK + i);
            x += v.x; y += v.y;
        }
        unsigned hh, ll;
        split2(x, y, hh, ll);
        *(unsigned*)(g_k_hi + i) = hh;
        *(unsigned*)(g_k_lo + i) = ll;
    } else {
        int r = bid - 8128;
        size_t i = (size_t)r * INNER + t * 2;
        const size_t NQ = (size_t)N_SEQ * INNER;
        float x = 0.f, y = 0.f;
#pragma unroll
        for (int p = 0; p < 12; p++) {
            float2 v = *(const float2*)(g_qp + p * NQ + i);
            x += v.x; y += v.y;
        }
        unsigned hh, ll;
        split2(x, y, hh, ll);
        *(unsigned*)(g_q_hi + i) = hh;
        *(unsigned*)(g_q_lo + i) = ll;
    }
}

// ---------------- attention v4 (R15, unchanged) ---------
#define AQ_H(st) ((st) * 8192)
#define AQ_L(st) (16384 + (st) * 8192)
#define AK_H(st) (32768 + (st) * 16384)
#define AK_L(st) (65536 + (st) * 16384)
#define A_FLT    98304
#define A_SMEM   (98304 + (128 + 1024 + 512 + 512) * 4)
#define SCL2     0.18033688011112042f

__global__ __launch_bounds__(256) void k_attn_mma(const int* __restrict__ mask,
                                                  float* __restrict__ out) {
    extern __shared__ char smc[];
    unsigned sb = smem_u32(smc);
    float* validS = (float*)(smc + A_FLT);
    float* vpsA   = validS + 128;
    float* SH     = vpsA + 1024;
    float* TH     = SH + 512;

    int c = blockIdx.x, n0 = blockIdx.y * 64;
    int t = threadIdx.x;
    int warp = t >> 5, lane = t & 31;
    int wm = (warp & 1) * 32, wn = (warp >> 1) * 32;

    if (t < 128) validS[t] = (t == 0 || mask[t - 1] != 0) ? 1.f : 0.f;
    for (int i = t; i < 1024; i += 256) {
        int h = i >> 7, j = i & 127;
        vpsA[i] = (j == 0) ? g_vpnull[h] : g_vpt[((size_t)c * NH + h) * NJ + j - 1];
    }
    for (int i = t; i < 1024; i += 256) SH[i] = 0.f;

    int qrow = t >> 2, qc = (t & 3) * 8;
    const __nv_bfloat16* q_h = g_q_hi + (size_t)(n0 + qrow) * INNER + qc;
    const __nv_bfloat16* q_l = g_q_lo + (size_t)(n0 + qrow) * INNER + qc;
    unsigned q_d0 = sw128((unsigned)(qrow * 128 + (t & 3) * 16));
    unsigned q_d1 = sw128((unsigned)(qrow * 128 + (t & 3) * 16 + 64));
    int krow = t >> 1, kc0 = (t & 1) * 32;
    const __nv_bfloat16* k_h = (krow == 0) ? (g_nullk_hi + kc0)
        : (g_k_hi + (size_t)(c * NJ + krow - 1) * INNER + kc0);
    const __nv_bfloat16* k_l = (krow == 0) ? (g_nullk_lo + kc0)
        : (g_k_lo + (size_t)(c * NJ + krow - 1) * INNER + kc0);
    unsigned k_d[4];
#pragma unroll
    for (int j = 0; j < 4; j++)
        k_d[j] = sw128((unsigned)(krow * 128 + (kc0 + j * 8) * 2));

    auto stage = [&](int h, int st) {
        cpa16(sb + AQ_H(st) + q_d0, q_h + h * HD);
        cpa16(sb + AQ_H(st) + q_d1, q_h + h * HD + 32);
        cpa16(sb + AQ_L(st) + q_d0, q_l + h * HD);
        cpa16(sb + AQ_L(st) + q_d1, q_l + h * HD + 32);
#pragma unroll
        for (int j = 0; j < 4; j++) {
            cpa16(sb + AK_H(st) + k_d[j], k_h + h * HD + j * 8);
            cpa16(sb + AK_L(st) + k_d[j], k_l + h * HD + j * 8);
        }
        CPA_COMMIT();
    };

    stage(0, 0);
    CPA_WAIT0();
    __syncthreads();

    for (int h = 0; h < NH; h++) {
        int st = h & 1;
        if (h + 1 < NH) stage(h + 1, st ^ 1);

        float D[2][4][4];
#pragma unroll
        for (int i = 0; i < 2; i++)
#pragma unroll
            for (int j = 0; j < 4; j++)
#pragma unroll
                for (int k = 0; k < 4; k++) D[i][j][k] = 0.f;
#pragma unroll
        for (int ks = 0; ks < 64; ks += 16) {
            unsigned ah[2][4], al[2][4];
#pragma unroll
            for (int mt = 0; mt < 2; mt++) {
                unsigned rel = sw128((unsigned)((wm + mt * 16 + (lane & 15)) * 128
                                                + (ks + (lane >> 4) * 8) * 2));
                ldm_x4(ah[mt], sb + AQ_H(st) + rel);
                ldm_x4(al[mt], sb + AQ_L(st) + rel);
            }
#pragma unroll
            for (int p = 0; p < 2; p++) {
                unsigned row = (unsigned)(wn + p * 16 + ((lane >> 4) << 3) + (lane & 7));
                unsigned rel = sw128(row * 128
                                     + (unsigned)((ks + ((lane >> 3) & 1) * 8) * 2));
                unsigned bh[4], bl[4];
                ldm_x4(bh, sb + AK_H(st) + rel);
                mma_bf16(D[0][2*p],   ah[0], bh);
                mma_bf16(D[1][2*p],   ah[1], bh);
                mma_bf16(D[0][2*p],   al[0], bh);
                mma_bf16(D[1][2*p],   al[1], bh);
                mma_bf16(D[0][2*p+1], ah[0], bh + 2);
                mma_bf16(D[1][2*p+1], ah[1], bh + 2);
                mma_bf16(D[0][2*p+1], al[0], bh + 2);
                mma_bf16(D[1][2*p+1], al[1], bh + 2);
                ldm_x4(bl, sb + AK_L(st) + rel);
                mma_bf16(D[0][2*p],   ah[0], bl);
                mma_bf16(D[1][2*p],   ah[1], bl);
                mma_bf16(D[0][2*p+1], ah[0], bl + 2);
                mma_bf16(D[1][2*p+1], ah[1], bl + 2);
            }
        }

        float rS[2][2], rT[2][2];
#pragma unroll
        for (int mt = 0; mt < 2; mt++) { rS[mt][0] = rS[mt][1] = rT[mt][0] = rT[mt][1] = 0.f; }
#pragma unroll
        for (int nt = 0; nt < 4; nt++) {
            int c0 = wn + nt * 8 + 2 * (lane & 3);
            float vl0 = validS[c0], vl1 = validS[c0 + 1];
            float vp0 = vpsA[h * 128 + c0], vp1 = vpsA[h * 128 + c0 + 1];
#pragma unroll
            for (int mt = 0; mt < 2; mt++) {
                float e00 = vl0 * fexp2(D[mt][nt][0] * SCL2);
                float e01 = vl1 * fexp2(D[mt][nt][1] * SCL2);
                float e10 = vl0 * fexp2(D[mt][nt][2] * SCL2);
                float e11 = vl1 * fexp2(D[mt][nt][3] * SCL2);
                rS[mt][0] += e00 + e01;
                rT[mt][0] += e00 * vp0 + e01 * vp1;
                rS[mt][1] += e10 + e11;
                rT[mt][1] += e10 * vp0 + e11 * vp1;
            }
        }
#pragma unroll
        for (int mt = 0; mt < 2; mt++)
#pragma unroll
            for (int half = 0; half < 2; half++) {
                float s = rS[mt][half], tt = rT[mt][half];
                s  += __shfl_xor_sync(0xffffffffu, s, 1);
                s  += __shfl_xor_sync(0xffffffffu, s, 2);
                tt += __shfl_xor_sync(0xffffffffu, tt, 1);
                tt += __shfl_xor_sync(0xffffffffu, tt, 2);
                if ((lane & 3) == 0) {
                    int row = wm + mt * 16 + (lane >> 2) + half * 8;
                    atomicAdd(&SH[h * 64 + row], s);
                    atomicAdd(&TH[h * 64 + row], tt);
                }
            }

        if (h + 1 < NH) { CPA_WAIT0(); }
        __syncthreads();
    }

    if (t < 64) {
        float racc = 0.f;
#pragma unroll
        for (int h = 0; h < NH; h++)
            racc += TH[h * 64 + t] / SH[h * 64 + t];
        int n = n0 + t;
        float x = g_ep[n] + g_bias + racc;
        out[(size_t)n * NC + c] = fmaxf(x, 0.f) + log1pf(__expf(-fabsf(x)));
    }
}

// ---------------- launch: dual-stream fork/join ----------------
static cudaStream_t s2 = 0;
static cudaEvent_t  e_fork = 0, e_join = 0;

extern "C" void kernel_launch(void* const* d_in, const int* in_sizes, int n_in,
                              void* d_out, int out_size) {
    const float* emb      = (const float*)d_in[0];
    const float* ctx      = (const float*)d_in[1];
    const int*   cmask    = (const int*)d_in[2];
    const float* q_gamma  = (const float*)d_in[3];
    const float* q_beta   = (const float*)d_in[4];
    const float* kv_gamma = (const float*)d_in[5];
    const float* kv_beta  = (const float*)d_in[6];
    const float* Wq       = (const float*)d_in[7];
    const float* Wkv      = (const float*)d_in[8];
    const float* null_k   = (const float*)d_in[9];
    const float* null_v   = (const float*)d_in[10];
    const float* Wo       = (const float*)d_in[11];
    const float* bo       = (const float*)d_in[12];
    const float* Wp       = (const float*)d_in[13];
    const float* bp       = (const float*)d_in[14];
    float* out = (float*)d_out;

    if (!s2) {
        cudaStreamCreateWithFlags(&s2, cudaStreamNonBlocking);
        cudaEventCreateWithFlags(&e_fork, cudaEventDisableTiming);
        cudaEventCreateWithFlags(&e_join, cudaEventDisableTiming);
        cudaFuncSetAttribute(k_attn_mma, cudaFuncAttributeMaxDynamicSharedMemorySize, A_SMEM);
        cudaFuncSetAttribute(k_gemm_mma, cudaFuncAttributeMaxDynamicSharedMemorySize, G2_SMEM);
    }

    // fork: side chain (dots -> prep2 -> ln_c) on s2
    cudaEventRecord(e_fork, 0);
    cudaStreamWaitEvent(s2, e_fork, 0);
    k_dots<<<513, 256, 0, s2>>>(Wo, Wp, bo, bp);
    k_prep2<<<33, 256, 0, s2>>>(Wkv, null_v, null_k);
    k_ln_c<<<MPAD / 8, 256, 0, s2>>>(ctx, kv_gamma, kv_beta);
    cudaEventRecord(e_join, s2);

    // main chain
    k_megaB<<<N_SEQ + 2048, 256>>>(emb, q_gamma, q_beta, Wp, Wkv, Wq);
    cudaStreamWaitEvent(0, e_join, 0);
    k_gemm_mma<<<1024 + 336, 512, G2_SMEM>>>();
    k_comb<<<8128 + N_SEQ, 256>>>();
    k_attn_mma<<<dim3(NC, N_SEQ / 64), 256, A_SMEM>>>(cmask, out);
}

// round 17
// speedup vs baseline: 1.0647x; 1.0647x over previous
#include <cuda_runtime.h>
#include <cuda_bf16.h>
#include <math.h>

#define N_SEQ 896
#define DH    3072
#define NC    64
#define NJ    127
#define DC    1024
#define INNER 512
#define NH    8
#define HD    64
#define MPAD  8192

// ---------------- scratch ----------------
__device__ float g_w[INNER];
__device__ float g_ep[N_SEQ];
__device__ float g_bias;
__device__ float g_wvpt[NH * DC];
__device__ float g_vpnull[NH];
__device__ float g_vpt[NC * NH * NJ];
__device__ __nv_bfloat16 g_nullk_hi[INNER];
__device__ __nv_bfloat16 g_nullk_lo[INNER];
__device__ float g_kp[(size_t)4 * MPAD * INNER];
__device__ float g_qp[(size_t)12 * N_SEQ * INNER];
__device__ __nv_bfloat16 g_a_hi[(size_t)MPAD * DC];
__device__ __nv_bfloat16 g_a_lo[(size_t)MPAD * DC];
__device__ __nv_bfloat16 g_aq_hi[(size_t)N_SEQ * DH];
__device__ __nv_bfloat16 g_aq_lo[(size_t)N_SEQ * DH];
__device__ __nv_bfloat16 g_wk_hi[(size_t)INNER * DC];
__device__ __nv_bfloat16 g_wk_lo[(size_t)INNER * DC];
__device__ __nv_bfloat16 g_wq_hi[(size_t)INNER * DH];
__device__ __nv_bfloat16 g_wq_lo[(size_t)INNER * DH];
__device__ __nv_bfloat16 g_q_hi[(size_t)N_SEQ * INNER];
__device__ __nv_bfloat16 g_q_lo[(size_t)N_SEQ * INNER];
__device__ __nv_bfloat16 g_k_hi[(size_t)MPAD * INNER];
__device__ __nv_bfloat16 g_k_lo[(size_t)MPAD * INNER];

__device__ __forceinline__ float warpSum(float v) {
#pragma unroll
    for (int o = 16; o > 0; o >>= 1) v += __shfl_xor_sync(0xffffffffu, v, o);
    return v;
}
__device__ __forceinline__ unsigned b2u(__nv_bfloat162 h) {
    return *reinterpret_cast<unsigned*>(&h);
}
__device__ __forceinline__ unsigned smem_u32(const void* p) {
    unsigned a;
    asm("{ .reg .u64 t; cvta.to.shared.u64 t, %1; cvt.u32.u64 %0, t; }" : "=r"(a) : "l"(p));
    return a;
}
__device__ __forceinline__ unsigned sw128(unsigned o) { return o ^ ((o >> 3) & 0x70); }
__device__ __forceinline__ unsigned pk(unsigned row, unsigned kbyte) {
    unsigned base = ((row >> 1) << 7) + ((row & 1) << 6) + kbyte;
    return base ^ ((base >> 3) & 0x70);
}
__device__ __forceinline__ float fexp2(float x) {
    float r; asm("ex2.approx.f32 %0, %1;" : "=f"(r) : "f"(x)); return r;
}
__device__ __forceinline__ void ldm_x4(unsigned* r, unsigned addr) {
    asm volatile("ldmatrix.sync.aligned.m8n8.x4.shared.b16 {%0,%1,%2,%3}, [%4];"
        : "=r"(r[0]), "=r"(r[1]), "=r"(r[2]), "=r"(r[3]) : "r"(addr));
}
__device__ __forceinline__ void mma_bf16(float* d, const unsigned* a, const unsigned* b) {
    asm volatile("mma.sync.aligned.m16n8k16.row.col.f32.bf16.bf16.f32 "
        "{%0,%1,%2,%3}, {%4,%5,%6,%7}, {%8,%9}, {%0,%1,%2,%3};"
        : "+f"(d[0]), "+f"(d[1]), "+f"(d[2]), "+f"(d[3])
        : "r"(a[0]), "r"(a[1]), "r"(a[2]), "r"(a[3]), "r"(b[0]), "r"(b[1]));
}
__device__ __forceinline__ void cpa16(unsigned dst, const void* src) {
    asm volatile("cp.async.cg.shared.global [%0], [%1], 16;" :: "r"(dst), "l"(src));
}
#define CPA_COMMIT() asm volatile("cp.async.commit_group;" ::: "memory")
#define CPA_WAIT1()  asm volatile("cp.async.wait_group 1;" ::: "memory")
#define CPA_WAIT0()  asm volatile("cp.async.wait_group 0;" ::: "memory")

__device__ __forceinline__ void split2(float x, float y, unsigned& hi, unsigned& lo) {
    __nv_bfloat162 h = __float22bfloat162_rn(make_float2(x, y));
    __nv_bfloat162 l = __float22bfloat162_rn(make_float2(
        x - __bfloat162float(h.x), y - __bfloat162float(h.y)));
    hi = b2u(h); lo = b2u(l);
}

// ---------------- mega prologue (R15) --------------------------------------------
__global__ void k_mega1(const float* __restrict__ emb, const float* __restrict__ gamma,
                        const float* __restrict__ beta, const float* __restrict__ Wo,
                        const float* __restrict__ Wp, const float* __restrict__ bo,
                        const float* __restrict__ bp, const float* __restrict__ Wkv,
                        const float* __restrict__ Wq) {
    __shared__ float row[DH];
    __shared__ float red[26];
    int bid = blockIdx.x, t = threadIdx.x;

    if (bid < N_SEQ) {
        const float* xr = emb + (size_t)bid * DH;
        float s = 0.f, ss = 0.f, se = 0.f;
#pragma unroll
        for (int u = 0; u < 3; u++) {
            int idx = (t + u * 256) * 4;
            float4 v = *(const float4*)(xr + idx);
            float4 w = *(const float4*)(Wp + idx);
            row[idx] = v.x; row[idx+1] = v.y; row[idx+2] = v.z; row[idx+3] = v.w;
            s  += v.x + v.y + v.z + v.w;
            ss += v.x*v.x + v.y*v.y + v.z*v.z + v.w*v.w;
            se += v.x*w.x + v.y*w.y + v.z*w.z + v.w*w.w;
        }
        s = warpSum(s); ss = warpSum(ss); se = warpSum(se);
        if ((t & 31) == 0) { int w8 = t >> 5; red[w8] = s; red[8+w8] = ss; red[16+w8] = se; }
        __syncthreads();
        if (t == 0) {
            float S = 0.f, SS = 0.f, SE = 0.f;
#pragma unroll
            for (int i = 0; i < 8; i++) { S += red[i]; SS += red[8+i]; SE += red[16+i]; }
            float mu = S / DH;
            float var = SS / DH - mu * mu;
            red[24] = mu; red[25] = rsqrtf(var + 1e-5f);
            g_ep[bid] = SE;
        }
        __syncthreads();
        float mu = red[24], rstd = red[25];
#pragma unroll
        for (int u = 0; u < 3; u++) {
            int idx = (t + u * 256) * 4;
            float o0 = (row[idx]   - mu) * rstd * gamma[idx]   + beta[idx];
            float o1 = (row[idx+1] - mu) * rstd * gamma[idx+1] + beta[idx+1];
            float o2 = (row[idx+2] - mu) * rstd * gamma[idx+2] + beta[idx+2];
            float o3 = (row[idx+3] - mu) * rstd * gamma[idx+3] + beta[idx+3];
            unsigned h01, l01, h23, l23;
            split2(o0, o1, h01, l01); split2(o2, o3, h23, l23);
            size_t off = (size_t)bid * DH + idx;
            *(uint2*)(g_aq_hi + off) = make_uint2(h01, h23);
            *(uint2*)(g_aq_lo + off) = make_uint2(l01, l23);
        }
        return;
    }
    if (bid < 1409) {
        int id = bid - N_SEQ;
        const float* a = (id < 512) ? (Wo + (size_t)id * DH) : bo;
        float s = 0.f;
        for (int i = t; i < DH; i += 256) s = fmaf(a[i], Wp[i], s);
        s = warpSum(s);
        if ((t & 31) == 0) red[t >> 5] = s;
        __syncthreads();
        if (t == 0) {
            float S = 0.f;
#pragma unroll
            for (int i = 0; i < 8; i++) S += red[i];
            if (id < 512) g_w[id] = S;
            else          g_bias = S + bp[0];
        }
        return;
    }
    {
        float (*tile)[33] = (float(*)[33])row;
        const float* src; __nv_bfloat16 *dh, *dl;
        int K, ldsrc, k0, n0;
        if (bid < 1921) {
            int l = bid - 1409;
            K = DC; ldsrc = 2 * INNER; src = Wkv; dh = g_wk_hi; dl = g_wk_lo;
            k0 = (l & 31) * 32; n0 = (l >> 5) * 32;
        } else {
            int l = bid - 1921;
            K = DH; ldsrc = INNER; src = Wq; dh = g_wq_hi; dl = g_wq_lo;
            k0 = (l % 96) * 32; n0 = (l / 96) * 32;
        }
        int tx = t & 31, ty = t >> 5;
#pragma unroll
        for (int r = 0; r < 4; r++)
            tile[ty + 8 * r][tx] = src[(size_t)(k0 + ty + 8 * r) * ldsrc + n0 + tx];
        __syncthreads();
#pragma unroll
        for (int r = 0; r < 4; r++) {
            int n = n0 + ty + 8 * r;
            float v = tile[tx][ty + 8 * r];
            __nv_bfloat16 h = __float2bfloat16_rn(v);
            __nv_bfloat16 l2 = __float2bfloat16_rn(v - __bfloat162float(h));
            dh[(size_t)n * K + k0 + tx] = h;
            dl[(size_t)n * K + k0 + tx] = l2;
        }
    }
}

// ---------------- prep 2 ----------------
__global__ void k_prep2(const float* __restrict__ Wkv, const float* __restrict__ null_v,
                        const float* __restrict__ null_k) {
    int bid = blockIdx.x, t = threadIdx.x;
    if (bid < 32) {
        int gid = bid * 256 + t;
        int h = gid >> 10, i = gid & 1023;
        const float* wrow = g_w + h * HD;
        const float* src  = Wkv + (size_t)i * (2 * INNER) + INNER + h * HD;
        float s = 0.f;
#pragma unroll
        for (int d = 0; d < HD; d++) s = fmaf(src[d], wrow[d], s);
        g_wvpt[h * DC + i] = s;
    } else {
        if (t < NH) {
            float s = 0.f;
#pragma unroll
            for (int d = 0; d < HD; d++) s = fmaf(null_v[t * HD + d], g_w[t * HD + d], s);
            g_vpnull[t] = s;
        }
        for (int i = t; i < INNER; i += 256) {
            float v = null_k[i];
            __nv_bfloat16 hb = __float2bfloat16_rn(v);
            g_nullk_hi[i] = hb;
            g_nullk_lo[i] = __float2bfloat16_rn(v - __bfloat162float(hb));
        }
    }
}

// ---------------- LN over context rows ----------------
__global__ __launch_bounds__(256) void k_ln_c(const float* __restrict__ x,
                                              const float* __restrict__ gamma,
                                              const float* __restrict__ beta) {
    __shared__ float wvs[NH * DC];
    int t = threadIdx.x, warp = t >> 5, lane = t & 31;
    for (int i = t; i < NH * DC; i += 256) wvs[i] = g_wvpt[i];
    __syncthreads();

    int b = blockIdx.x * 8 + warp;
    if (b >= NC * NJ) {
        if (b < MPAD) {
            uint2 z = make_uint2(0u, 0u);
#pragma unroll
            for (int c = 0; c < 8; c++) {
                size_t off = (size_t)b * DC + c * 128 + lane * 4;
                *(uint2*)(g_a_hi + off) = z;
                *(uint2*)(g_a_lo + off) = z;
            }
        }
        return;
    }
    const float* xr = x + (size_t)b * DC;
    float4 r[8];
    float s = 0.f, ss = 0.f;
#pragma unroll
    for (int c = 0; c < 8; c++) {
        r[c] = *(const float4*)(xr + c * 128 + lane * 4);
        s  += r[c].x + r[c].y + r[c].z + r[c].w;
        ss += r[c].x*r[c].x + r[c].y*r[c].y + r[c].z*r[c].z + r[c].w*r[c].w;
    }
    s = warpSum(s); ss = warpSum(ss);
    float mu = s / DC;
    float rstd = rsqrtf(ss / DC - mu * mu + 1e-5f);
#pragma unroll
    for (int c = 0; c < 8; c++) {
        int idx = c * 128 + lane * 4;
        float4 g = *(const float4*)(gamma + idx);
        float4 bb = *(const float4*)(beta + idx);
        r[c].x = (r[c].x - mu) * rstd * g.x + bb.x;
        r[c].y = (r[c].y - mu) * rstd * g.y + bb.y;
        r[c].z = (r[c].z - mu) * rstd * g.z + bb.z;
        r[c].w = (r[c].w - mu) * rstd * g.w + bb.w;
        unsigned h01, l01, h23, l23;
        split2(r[c].x, r[c].y, h01, l01); split2(r[c].z, r[c].w, h23, l23);
        size_t off = (size_t)b * DC + idx;
        *(uint2*)(g_a_hi + off) = make_uint2(h01, h23);
        *(uint2*)(g_a_lo + off) = make_uint2(l01, l23);
    }
    int cc = b / NJ, j = b % NJ;
#pragma unroll
    for (int h = 0; h < NH; h++) {
        float acc = 0.f;
#pragma unroll
        for (int c = 0; c < 8; c++) {
            int idx = h * DC + c * 128 + lane * 4;
            acc = fmaf(r[c].x, wvs[idx],   acc);
            acc = fmaf(r[c].y, wvs[idx+1], acc);
            acc = fmaf(r[c].z, wvs[idx+2], acc);
            acc = fmaf(r[c].w, wvs[idx+3], acc);
        }
        acc = warpSum(acc);
        if (lane == 0) g_vpt[((size_t)cc * NH + h) * NJ + j] = acc;
    }
}

// ---------------- HMMA GEMM v7 (R15, unchanged) ----------
#define G2_AH 0
#define G2_AL 8192
#define G2_BH 16384
#define G2_BL 24576
#define G2_ST 32768
#define G2_SMEM (3 * G2_ST)

__global__ void __launch_bounds__(512, 2) k_gemm_mma() {
    extern __shared__ char smg[];
    unsigned sb = smem_u32(smg);
    int t = threadIdx.x, bid = blockIdx.x;

    const __nv_bfloat16 *Ahp, *Alp, *Bhp, *Blp;
    float* P;
    int Kb, m0, n0, kbase;
    if (bid < 1024) {
        int part = bid >> 8, r = bid & 255;
        m0 = (r >> 2) * 128; n0 = (r & 3) * 128;
        Ahp = g_a_hi; Alp = g_a_lo; Kb = DC; kbase = part * 256;
        Bhp = g_wk_hi; Blp = g_wk_lo;
        P = g_kp + (size_t)part * MPAD * INNER;
    } else {
        int l = bid - 1024;
        int part = l / 28, r = l % 28;
        m0 = (r >> 2) * 128; n0 = (r & 3) * 128;
        Ahp = g_aq_hi; Alp = g_aq_lo; Kb = DH; kbase = part * 256;
        Bhp = g_wq_hi; Blp = g_wq_lo;
        P = g_qp + (size_t)part * N_SEQ * INNER;
    }
    int warp = t >> 5, lane = t & 31;
    int wm = (warp & 3) * 32, wn = (warp >> 2) * 32;

    float D[2][4][4];
#pragma unroll
    for (int i = 0; i < 2; i++)
#pragma unroll
        for (int j = 0; j < 4; j++)
#pragma unroll
            for (int k = 0; k < 4; k++) D[i][j][k] = 0.f;

    int sr = t >> 2, sc = (t & 3) * 8;
    unsigned sdst = pk((unsigned)sr, (unsigned)((t & 3) * 16));
    const __nv_bfloat16* a_h = Ahp + (size_t)(m0 + sr) * Kb + kbase + sc;
    const __nv_bfloat16* a_l = Alp + (size_t)(m0 + sr) * Kb + kbase + sc;
    const __nv_bfloat16* b_h = Bhp + (size_t)(n0 + sr) * Kb + kbase + sc;
    const __nv_bfloat16* b_l = Blp + (size_t)(n0 + sr) * Kb + kbase + sc;

    const int S = 8;
    auto issue = [&](int k0, int st) {
        unsigned base = sb + st * G2_ST;
        cpa16(base + G2_AH + sdst, a_h + k0);
        cpa16(base + G2_AL + sdst, a_l + k0);
        cpa16(base + G2_BH + sdst, b_h + k0);
        cpa16(base + G2_BL + sdst, b_l + k0);
        CPA_COMMIT();
    };

    issue(0, 0);
    issue(32, 1);
    for (int s = 0; s < S; s++) {
        if (s < S - 1) CPA_WAIT1(); else CPA_WAIT0();
        __syncthreads();
        if (s + 2 < S) issue((s + 2) * 32, (s + 2) % 3);
        unsigned ab = sb + (s % 3) * G2_ST;
#pragma unroll
        for (int ks = 0; ks < 32; ks += 16) {
            unsigned ah[2][4], al[2][4];
#pragma unroll
            for (int mt = 0; mt < 2; mt++) {
                unsigned ad = pk((unsigned)(wm + mt * 16 + (lane & 15)),
                                 (unsigned)((ks + (lane >> 4) * 8) * 2));
                ldm_x4(ah[mt], ab + G2_AH + ad);
                ldm_x4(al[mt], ab + G2_AL + ad);
            }
#pragma unroll
            for (int p = 0; p < 2; p++) {
                unsigned row = (unsigned)(wn + p * 16 + ((lane >> 4) << 3) + (lane & 7));
                unsigned bd = pk(row, (unsigned)((ks + ((lane >> 3) & 1) * 8) * 2));
                unsigned bh[4], bl[4];
                ldm_x4(bh, ab + G2_BH + bd);
                mma_bf16(D[0][2*p],   ah[0], bh);
                mma_bf16(D[1][2*p],   ah[1], bh);
                mma_bf16(D[0][2*p],   al[0], bh);
                mma_bf16(D[1][2*p],   al[1], bh);
                mma_bf16(D[0][2*p+1], ah[0], bh + 2);
                mma_bf16(D[1][2*p+1], ah[1], bh + 2);
                mma_bf16(D[0][2*p+1], al[0], bh + 2);
                mma_bf16(D[1][2*p+1], al[1], bh + 2);
                ldm_x4(bl, ab + G2_BL + bd);
                mma_bf16(D[0][2*p],   ah[0], bl);
                mma_bf16(D[1][2*p],   ah[1], bl);
                mma_bf16(D[0][2*p+1], ah[0], bl + 2);
                mma_bf16(D[1][2*p+1], ah[1], bl + 2);
            }
        }
    }
#pragma unroll
    for (int mt = 0; mt < 2; mt++) {
        int r0 = m0 + wm + mt * 16 + (lane >> 2);
#pragma unroll
        for (int nt = 0; nt < 4; nt++) {
            int col = n0 + wn + nt * 8 + 2 * (lane & 3);
#pragma unroll
            for (int half = 0; half < 2; half++) {
                *(float2*)(P + (size_t)(r0 + half * 8) * INNER + col) =
                    make_float2(D[mt][nt][half * 2], D[mt][nt][half * 2 + 1]);
            }
        }
    }
}

// ---------------- split-K combine ----
__global__ __launch_bounds__(256) void k_comb() {
    int bid = blockIdx.x, t = threadIdx.x;
    if (bid < 8128) {
        size_t i = (size_t)bid * INNER + t * 2;
        const size_t NK = (size_t)MPAD * INNER;
        float x = 0.f, y = 0.f;
#pragma unroll
        for (int p = 0; p < 4; p++) {
            float2 v = *(const float2*)(g_kp + p * NK + i);
            x += v.x; y += v.y;
        }
        unsigned hh, ll;
        split2(x, y, hh, ll);
        *(unsigned*)(g_k_hi + i) = hh;
        *(unsigned*)(g_k_lo + i) = ll;
    } else {
        int r = bid - 8128;
        size_t i = (size_t)r * INNER + t * 2;
        const size_t NQ = (size_t)N_SEQ * INNER;
        float x = 0.f, y = 0.f;
#pragma unroll
        for (int p = 0; p < 12; p++) {
            float2 v = *(const float2*)(g_qp + p * NQ + i);
            x += v.x; y += v.y;
        }
        unsigned hh, ll;
        split2(x, y, hh, ll);
        *(unsigned*)(g_q_hi + i) = hh;
        *(unsigned*)(g_q_lo + i) = ll;
    }
}

// ---------------- attention v5: 512 threads, 128-row q-tile ---------
// smem: QH 2x16K @0, QL 2x16K @32K, KH 2x16K @64K, KL 2x16K @96K; floats @128K
#define AQ_H(st) ((st) * 16384)
#define AQ_L(st) (32768 + (st) * 16384)
#define AK_H(st) (65536 + (st) * 16384)
#define AK_L(st) (98304 + (st) * 16384)
#define A_FLT    131072
#define A_SMEM   (131072 + (128 + 1024 + 1024 + 1024) * 4)
#define SCL2     0.18033688011112042f

__global__ __launch_bounds__(512) void k_attn_mma(const int* __restrict__ mask,
                                                  float* __restrict__ out) {
    extern __shared__ char smc[];
    unsigned sb = smem_u32(smc);
    float* validS = (float*)(smc + A_FLT);
    float* vpsA   = validS + 128;
    float* SH     = vpsA + 1024;
    float* TH     = SH + 1024;

    int c = blockIdx.x, n0 = blockIdx.y * 128;
    int t = threadIdx.x;
    int warp = t >> 5, lane = t & 31;
    int wm = (warp & 3) * 32, wn = (warp >> 2) * 32;

    if (t < 128) validS[t] = (t == 0 || mask[t - 1] != 0) ? 1.f : 0.f;
#pragma unroll
    for (int i = t; i < 1024; i += 512) {
        int h = i >> 7, j = i & 127;
        vpsA[i] = (j == 0) ? g_vpnull[h] : g_vpt[((size_t)c * NH + h) * NJ + j - 1];
    }
#pragma unroll
    for (int i = t; i < 2048; i += 512) SH[i] = 0.f;   // SH+TH contiguous

    // staging: t>>2 = row (0..127), chunks (t&3) and (t&3)+4 of 8 per row
    int qrow = t >> 2, qc = (t & 3) * 8;
    const __nv_bfloat16* q_h = g_q_hi + (size_t)(n0 + qrow) * INNER + qc;
    const __nv_bfloat16* q_l = g_q_lo + (size_t)(n0 + qrow) * INNER + qc;
    unsigned d0 = sw128((unsigned)(qrow * 128 + (t & 3) * 16));
    unsigned d1 = sw128((unsigned)(qrow * 128 + (t & 3) * 16 + 64));
    int krow = qrow;
    const __nv_bfloat16* k_h = (krow == 0) ? (g_nullk_hi + qc)
        : (g_k_hi + (size_t)(c * NJ + krow - 1) * INNER + qc);
    const __nv_bfloat16* k_l = (krow == 0) ? (g_nullk_lo + qc)
        : (g_k_lo + (size_t)(c * NJ + krow - 1) * INNER + qc);

    auto stage = [&](int h, int st) {
        cpa16(sb + AQ_H(st) + d0, q_h + h * HD);
        cpa16(sb + AQ_H(st) + d1, q_h + h * HD + 32);
        cpa16(sb + AQ_L(st) + d0, q_l + h * HD);
        cpa16(sb + AQ_L(st) + d1, q_l + h * HD + 32);
        cpa16(sb + AK_H(st) + d0, k_h + h * HD);
        cpa16(sb + AK_H(st) + d1, k_h + h * HD + 32);
        cpa16(sb + AK_L(st) + d0, k_l + h * HD);
        cpa16(sb + AK_L(st) + d1, k_l + h * HD + 32);
        CPA_COMMIT();
    };

    stage(0, 0);
    CPA_WAIT0();
    __syncthreads();

    for (int h = 0; h < NH; h++) {
        int st = h & 1;
        if (h + 1 < NH) stage(h + 1, st ^ 1);

        float D[2][4][4];
#pragma unroll
        for (int i = 0; i < 2; i++)
#pragma unroll
            for (int j = 0; j < 4; j++)
#pragma unroll
                for (int k = 0; k < 4; k++) D[i][j][k] = 0.f;
#pragma unroll
        for (int ks = 0; ks < 64; ks += 16) {
            unsigned ah[2][4], al[2][4];
#pragma unroll
            for (int mt = 0; mt < 2; mt++) {
                unsigned rel = sw128((unsigned)((wm + mt * 16 + (lane & 15)) * 128
                                                + (ks + (lane >> 4) * 8) * 2));
                ldm_x4(ah[mt], sb + AQ_H(st) + rel);
                ldm_x4(al[mt], sb + AQ_L(st) + rel);
            }
#pragma unroll
            for (int p = 0; p < 2; p++) {
                unsigned row = (unsigned)(wn + p * 16 + ((lane >> 4) << 3) + (lane & 7));
                unsigned rel = sw128(row * 128
                                     + (unsigned)((ks + ((lane >> 3) & 1) * 8) * 2));
                unsigned bh[4], bl[4];
                ldm_x4(bh, sb + AK_H(st) + rel);
                mma_bf16(D[0][2*p],   ah[0], bh);
                mma_bf16(D[1][2*p],   ah[1], bh);
                mma_bf16(D[0][2*p],   al[0], bh);
                mma_bf16(D[1][2*p],   al[1], bh);
                mma_bf16(D[0][2*p+1], ah[0], bh + 2);
                mma_bf16(D[1][2*p+1], ah[1], bh + 2);
                mma_bf16(D[0][2*p+1], al[0], bh + 2);
                mma_bf16(D[1][2*p+1], al[1], bh + 2);
                ldm_x4(bl, sb + AK_L(st) + rel);
                mma_bf16(D[0][2*p],   ah[0], bl);
                mma_bf16(D[1][2*p],   ah[1], bl);
                mma_bf16(D[0][2*p+1], ah[0], bl + 2);
                mma_bf16(D[1][2*p+1], ah[1], bl + 2);
            }
        }

        float rS[2][2], rT[2][2];
#pragma unroll
        for (int mt = 0; mt < 2; mt++) { rS[mt][0] = rS[mt][1] = rT[mt][0] = rT[mt][1] = 0.f; }
#pragma unroll
        for (int nt = 0; nt < 4; nt++) {
            int c0 = wn + nt * 8 + 2 * (lane & 3);
            float vl0 = validS[c0], vl1 = validS[c0 + 1];
            float vp0 = vpsA[h * 128 + c0], vp1 = vpsA[h * 128 + c0 + 1];
#pragma unroll
            for (int mt = 0; mt < 2; mt++) {
                float e00 = vl0 * fexp2(D[mt][nt][0] * SCL2);
                float e01 = vl1 * fexp2(D[mt][nt][1] * SCL2);
                float e10 = vl0 * fexp2(D[mt][nt][2] * SCL2);
                float e11 = vl1 * fexp2(D[mt][nt][3] * SCL2);
                rS[mt][0] += e00 + e01;
                rT[mt][0] += e00 * vp0 + e01 * vp1;
                rS[mt][1] += e10 + e11;
                rT[mt][1] += e10 * vp0 + e11 * vp1;
            }
        }
#pragma unroll
        for (int mt = 0; mt < 2; mt++)
#pragma unroll
            for (int half = 0; half < 2; half++) {
                float s = rS[mt][half], tt = rT[mt][half];
                s  += __shfl_xor_sync(0xffffffffu, s, 1);
                s  += __shfl_xor_sync(0xffffffffu, s, 2);
                tt += __shfl_xor_sync(0xffffffffu, tt, 1);
                tt += __shfl_xor_sync(0xffffffffu, tt, 2);
                if ((lane & 3) == 0) {
                    int row = wm + mt * 16 + (lane >> 2) + half * 8;
                    atomicAdd(&SH[h * 128 + row], s);
                    atomicAdd(&TH[h * 128 + row], tt);
                }
            }

        if (h + 1 < NH) { CPA_WAIT0(); }
        __syncthreads();
    }

    if (t < 128) {
        float racc = 0.f;
#pragma unroll
        for (int h = 0; h < NH; h++)
            racc += TH[h * 128 + t] / SH[h * 128 + t];
        int n = n0 + t;
        float x = g_ep[n] + g_bias + racc;
        out[(size_t)n * NC + c] = fmaxf(x, 0.f) + log1pf(__expf(-fabsf(x)));
    }
}

// ---------------- launch (single stream, R15 structure) ----------------
extern "C" void kernel_launch(void* const* d_in, const int* in_sizes, int n_in,
                              void* d_out, int out_size) {
    const float* emb      = (const float*)d_in[0];
    const float* ctx      = (const float*)d_in[1];
    const int*   cmask    = (const int*)d_in[2];
    const float* q_gamma  = (const float*)d_in[3];
    const float* q_beta   = (const float*)d_in[4];
    const float* kv_gamma = (const float*)d_in[5];
    const float* kv_beta  = (const float*)d_in[6];
    const float* Wq       = (const float*)d_in[7];
    const float* Wkv      = (const float*)d_in[8];
    const float* null_k   = (const float*)d_in[9];
    const float* null_v   = (const float*)d_in[10];
    const float* Wo       = (const float*)d_in[11];
    const float* bo       = (const float*)d_in[12];
    const float* Wp       = (const float*)d_in[13];
    const float* bp       = (const float*)d_in[14];
    float* out = (float*)d_out;

    cudaFuncSetAttribute(k_attn_mma, cudaFuncAttributeMaxDynamicSharedMemorySize, A_SMEM);
    cudaFuncSetAttribute(k_gemm_mma, cudaFuncAttributeMaxDynamicSharedMemorySize, G2_SMEM);

    k_mega1<<<3457, 256>>>(emb, q_gamma, q_beta, Wo, Wp, bo, bp, Wkv, Wq);
    k_prep2<<<33, 256>>>(Wkv, null_v, null_k);
    k_ln_c<<<MPAD / 8, 256>>>(ctx, kv_gamma, kv_beta);
    k_gemm_mma<<<1024 + 336, 512, G2_SMEM>>>();
    k_comb<<<8128 + N_SEQ, 256>>>();
    k_attn_mma<<<dim3(NC, N_SEQ / 128), 512, A_SMEM>>>(cmask, out);
}